// round 2
// baseline (speedup 1.0000x reference)
#include <cuda_runtime.h>
#include <math.h>

// ---------------- problem-size scratch (static, no allocation) ----------------
#define NMAX 1000000
#define BMAX 16384

__device__ float g_t[BMAX * 64];        // t = u @ W1b + b1           [B,64]
__device__ float g_scores[NMAX];        // raw per-node scores        [N]
__device__ float g_x2[BMAX * 256];      // concat(u, pooled)          [B,256]
__device__ float g_h2[BMAX * 256];      // relu(x2@Wg1+bg1)           [B,256]
__device__ int   g_segstart[BMAX + 1];  // segment boundaries (batch sorted)

// ---------------- segment boundaries: one pass over sorted batch ----------------
__global__ void bounds_kernel(const int* __restrict__ batch, int N, int B) {
    int i = blockIdx.x * blockDim.x + threadIdx.x;
    if (i >= N) return;
    int bi = batch[i];
    int bprev = (i == 0) ? -1 : batch[i - 1];
    for (int g = bprev + 1; g <= bi; g++) g_segstart[g] = i;
    if (i == N - 1) {
        for (int g = bi + 1; g <= B; g++) g_segstart[g] = N;
    }
}

// ---------------- generic fp32 GEMM: C = [relu](A[M,K] @ Bm[K,Nn] + bias) ------
// 64x64 tile, k-chunk 16, 256 threads, 4x4 per-thread register blocking.
__global__ void __launch_bounds__(256) gemm_kernel(
    const float* __restrict__ A, const float* __restrict__ Bm,
    const float* __restrict__ bias, float* __restrict__ C,
    int M, int Nn, int K, int relu)
{
    __shared__ __align__(16) float As[16][68];
    __shared__ __align__(16) float Bs[16][64];
    int tid = threadIdx.x;
    int mBase = blockIdx.y * 64, nBase = blockIdx.x * 64;
    int tx = tid & 15, ty = tid >> 4;

    float acc[4][4];
#pragma unroll
    for (int i2 = 0; i2 < 4; i2++)
#pragma unroll
        for (int j2 = 0; j2 < 4; j2++) acc[i2][j2] = 0.f;

    for (int kk = 0; kk < K; kk += 16) {
#pragma unroll
        for (int r = 0; r < 4; r++) {
            int idx = r * 256 + tid;
            int m = idx >> 4, k = idx & 15;
            int gm = mBase + m;
            As[k][m] = (gm < M) ? A[(size_t)gm * K + kk + k] : 0.f;
        }
#pragma unroll
        for (int r = 0; r < 4; r++) {
            int idx = r * 256 + tid;
            int k = idx >> 6, n = idx & 63;
            int gn = nBase + n;
            Bs[k][n] = (gn < Nn) ? Bm[(size_t)(kk + k) * Nn + gn] : 0.f;
        }
        __syncthreads();
#pragma unroll
        for (int k = 0; k < 16; k++) {
            float4 av = *(const float4*)&As[k][ty * 4];
            float4 bv = *(const float4*)&Bs[k][tx * 4];
            float am[4] = {av.x, av.y, av.z, av.w};
            float bn[4] = {bv.x, bv.y, bv.z, bv.w};
#pragma unroll
            for (int i2 = 0; i2 < 4; i2++)
#pragma unroll
                for (int j2 = 0; j2 < 4; j2++)
                    acc[i2][j2] += am[i2] * bn[j2];
        }
        __syncthreads();
    }
#pragma unroll
    for (int i2 = 0; i2 < 4; i2++) {
        int gm = mBase + ty * 4 + i2;
        if (gm >= M) continue;
#pragma unroll
        for (int j2 = 0; j2 < 4; j2++) {
            int gn = nBase + tx * 4 + j2;
            if (gn >= Nn) continue;
            float v = acc[i2][j2] + bias[gn];
            if (relu) v = fmaxf(v, 0.f);
            C[(size_t)gm * Nn + gn] = v;
        }
    }
}

// ---------------- fused node-score kernel: scores = relu(x@W1a + t[batch])@W2 + b2
// Persistent blocks: W1a (128x64, 32KB) resident in smem for the whole kernel.
// Tile = 64 nodes; 256 threads; per-thread 4 nodes x 4 cols register blocking.
#define SC_SMEM_FLOATS (8192 /*ws*/ + 64 * 132 /*xs*/ )
#define SC_SMEM_BYTES  (SC_SMEM_FLOATS * 4 + 64 * 4 /*bs*/)

__global__ void __launch_bounds__(256) scores_kernel(
    const float* __restrict__ x, const int* __restrict__ batch,
    const float* __restrict__ W1, const float* __restrict__ W2,
    const float* __restrict__ b2, int N)
{
    extern __shared__ __align__(16) unsigned char smem_raw[];
    float* ws = (float*)smem_raw;            // [128][64]  W1a
    float* xs = ws + 8192;                   // [64][132]  x tile (padded stride)
    int*   bs = (int*)(xs + 64 * 132);       // [64]       batch ids

    int tid = threadIdx.x;
    // load W1a (rows 0..127 of W1, contiguous) once
    {
        const float4* src = (const float4*)W1;
        float4* dst = (float4*)ws;
        for (int i = tid; i < 8192 / 4; i += 256) dst[i] = src[i];
    }
    __syncthreads();

    int sub   = tid >> 6;        // 0..3  : which 16-node sub-tile
    int t64   = tid & 63;
    int cq    = t64 & 15;        // col quad (lane % 16)
    int nq    = t64 >> 4;        // node quad within sub-tile
    int j0    = cq * 4;
    int nbase = sub * 16 + nq * 4;

    float4 w2v = *(const float4*)&W2[j0];    // 4 W2 weights for this thread
    float  b2v = b2[0];

    int numTiles = (N + 63) >> 6;
    for (int tile = blockIdx.x; tile < numTiles; tile += gridDim.x) {
        int base = tile << 6;
        // stage 64 x-rows into smem (float4, padded row stride 132)
        for (int i = tid; i < 64 * 32; i += 256) {
            int n = i >> 5, c4 = i & 31;
            int gi = base + n;
            float4 v = make_float4(0.f, 0.f, 0.f, 0.f);
            if (gi < N) v = ((const float4*)x)[(size_t)gi * 32 + c4];
            *(float4*)&xs[n * 132 + c4 * 4] = v;
        }
        if (tid < 64) bs[tid] = (base + tid < N) ? batch[base + tid] : 0;
        __syncthreads();

        float acc[4][4];
#pragma unroll
        for (int a = 0; a < 4; a++) {
            float4 tv = *(const float4*)&g_t[(size_t)bs[nbase + a] * 64 + j0];
            acc[a][0] = tv.x; acc[a][1] = tv.y; acc[a][2] = tv.z; acc[a][3] = tv.w;
        }
#pragma unroll 4
        for (int k = 0; k < 128; k++) {
            float4 wv = *(const float4*)&ws[k * 64 + j0];
            float x0 = xs[(nbase + 0) * 132 + k];
            float x1 = xs[(nbase + 1) * 132 + k];
            float x2 = xs[(nbase + 2) * 132 + k];
            float x3 = xs[(nbase + 3) * 132 + k];
            acc[0][0] += x0 * wv.x; acc[0][1] += x0 * wv.y; acc[0][2] += x0 * wv.z; acc[0][3] += x0 * wv.w;
            acc[1][0] += x1 * wv.x; acc[1][1] += x1 * wv.y; acc[1][2] += x1 * wv.z; acc[1][3] += x1 * wv.w;
            acc[2][0] += x2 * wv.x; acc[2][1] += x2 * wv.y; acc[2][2] += x2 * wv.z; acc[2][3] += x2 * wv.w;
            acc[3][0] += x3 * wv.x; acc[3][1] += x3 * wv.y; acc[3][2] += x3 * wv.z; acc[3][3] += x3 * wv.w;
        }
#pragma unroll
        for (int a = 0; a < 4; a++) {
            float p = fmaxf(acc[a][0], 0.f) * w2v.x + fmaxf(acc[a][1], 0.f) * w2v.y
                    + fmaxf(acc[a][2], 0.f) * w2v.z + fmaxf(acc[a][3], 0.f) * w2v.w;
            p += __shfl_xor_sync(0xffffffffu, p, 8);
            p += __shfl_xor_sync(0xffffffffu, p, 4);
            p += __shfl_xor_sync(0xffffffffu, p, 2);
            p += __shfl_xor_sync(0xffffffffu, p, 1);
            if (cq == 0) {
                int gi = base + nbase + a;
                if (gi < N) g_scores[gi] = p + b2v;
            }
        }
        __syncthreads();
    }
}

// ---------------- per-graph softmax + weighted pooling + concat build ----------
__global__ void __launch_bounds__(128) pool_kernel(
    const float* __restrict__ x, const float* __restrict__ u,
    float* __restrict__ attn, int N, int B)
{
    int g = blockIdx.x;
    int s = g_segstart[g], e = g_segstart[g + 1];
    int tid = threadIdx.x;
    int lane = tid & 31, wid = tid >> 5;
    __shared__ float red[4];

    // segment max
    float m = -INFINITY;
    for (int i = s + tid; i < e; i += 128) m = fmaxf(m, g_scores[i]);
#pragma unroll
    for (int o = 16; o; o >>= 1) m = fmaxf(m, __shfl_xor_sync(0xffffffffu, m, o));
    if (lane == 0) red[wid] = m;
    __syncthreads();
    m = fmaxf(fmaxf(red[0], red[1]), fmaxf(red[2], red[3]));
    __syncthreads();

    // segment sum of exp
    float ssum = 0.f;
    for (int i = s + tid; i < e; i += 128) ssum += expf(g_scores[i] - m);
#pragma unroll
    for (int o = 16; o; o >>= 1) ssum += __shfl_xor_sync(0xffffffffu, ssum, o);
    if (lane == 0) red[wid] = ssum;
    __syncthreads();
    float denom = red[0] + red[1] + red[2] + red[3];
    float inv = (denom > 0.f) ? 1.f / denom : 0.f;

    // write attention weights
    for (int i = s + tid; i < e; i += 128) attn[i] = expf(g_scores[i] - m) * inv;
    __syncthreads();

    // weighted pool: thread = feature
    float pool = 0.f;
    for (int i = s; i < e; i++) pool += attn[i] * x[(size_t)i * 128 + tid];
    g_x2[(size_t)g * 256 + tid]       = u[(size_t)g * 128 + tid];
    g_x2[(size_t)g * 256 + 128 + tid] = pool;
}

// ---------------- launch -------------------------------------------------------
extern "C" void kernel_launch(void* const* d_in, const int* in_sizes, int n_in,
                              void* d_out, int out_size)
{
    const float* x     = (const float*)d_in[0];
    const float* u     = (const float*)d_in[3];
    const int*   batch = (const int*)d_in[4];
    const float* W1    = (const float*)d_in[5];
    const float* b1    = (const float*)d_in[6];
    const float* W2    = (const float*)d_in[7];
    const float* b2    = (const float*)d_in[8];
    const float* Wg1   = (const float*)d_in[9];
    const float* bg1   = (const float*)d_in[10];
    const float* Wg2   = (const float*)d_in[11];
    const float* bg2   = (const float*)d_in[12];

    int N = in_sizes[0] / 128;
    int B = in_sizes[3] / 128;

    float* out  = (float*)d_out;                      // [B,128]
    float* attn = (float*)d_out + (size_t)B * 128;    // [N]

    float *t_ptr, *x2_ptr, *h2_ptr;
    cudaGetSymbolAddress((void**)&t_ptr,  g_t);
    cudaGetSymbolAddress((void**)&x2_ptr, g_x2);
    cudaGetSymbolAddress((void**)&h2_ptr, g_h2);

    // 0) segment boundaries
    bounds_kernel<<<(N + 255) / 256, 256>>>(batch, N, B);

    // 1) t[B,64] = u @ W1b + b1   (W1b = rows 128..255 of W1, contiguous)
    {
        dim3 grid(1, (B + 63) / 64);
        gemm_kernel<<<grid, 256>>>(u, W1 + 128 * 64, b1, t_ptr, B, 64, 128, 0);
    }

    // 2) per-node scores (dominant GEMM, fused relu + W2 projection)
    cudaFuncSetAttribute(scores_kernel,
                         cudaFuncAttributeMaxDynamicSharedMemorySize, SC_SMEM_BYTES);
    scores_kernel<<<608, 256, SC_SMEM_BYTES>>>(x, batch, W1, W2, b2, N);

    // 3) segmented softmax + pooling, builds concat(u, pooled)
    pool_kernel<<<B, 128>>>(x, u, attn, N, B);

    // 4) global MLP: h2 = relu(x2@Wg1+bg1); out = h2@Wg2+bg2
    {
        dim3 g3a(256 / 64, (B + 63) / 64);
        gemm_kernel<<<g3a, 256>>>(x2_ptr, Wg1, bg1, h2_ptr, B, 256, 256, 1);
        dim3 g3b(128 / 64, (B + 63) / 64);
        gemm_kernel<<<g3b, 256>>>(h2_ptr, Wg2, bg2, out, B, 128, 256, 0);
    }
}

// round 4
// speedup vs baseline: 1.4405x; 1.4405x over previous
#include <cuda_runtime.h>
#include <cuda_bf16.h>
#include <math.h>
#include <stdint.h>

#define NMAX 1000000
#define BMAX 16384

__device__ float g_t[BMAX * 64];        // t = u @ W1b + b1           [B,64]
__device__ float g_scores[NMAX];        // raw per-node scores        [N]
__device__ float g_x2[BMAX * 256];      // concat(u, pooled)          [B,256]
__device__ float g_h2[BMAX * 256];      // relu(x2@Wg1+bg1)           [B,256]
__device__ int   g_segstart[BMAX + 1];  // segment boundaries

// ================= helpers =================
__device__ __forceinline__ uint32_t smem_u32(const void* p) {
    uint32_t a;
    asm("{ .reg .u64 t; cvta.to.shared.u64 t, %1; cvt.u32.u64 %0, t; }" : "=r"(a) : "l"(p));
    return a;
}

__device__ __forceinline__ void ldmat4(uint32_t* r, uint32_t addr) {
    asm volatile("ldmatrix.sync.aligned.m8n8.x4.shared.b16 {%0,%1,%2,%3}, [%4];"
        : "=r"(r[0]), "=r"(r[1]), "=r"(r[2]), "=r"(r[3]) : "r"(addr));
}

__device__ __forceinline__ void hmma(float* c, const uint32_t* a, uint32_t b0, uint32_t b1) {
    asm volatile(
        "mma.sync.aligned.m16n8k16.row.col.f32.bf16.bf16.f32 "
        "{%0,%1,%2,%3}, {%4,%5,%6,%7}, {%8,%9}, {%0,%1,%2,%3};"
        : "+f"(c[0]), "+f"(c[1]), "+f"(c[2]), "+f"(c[3])
        : "r"(a[0]), "r"(a[1]), "r"(a[2]), "r"(a[3]), "r"(b0), "r"(b1));
}

// ================= segment boundaries =================
__global__ void bounds_kernel(const int* __restrict__ batch, int N, int B) {
    int i = blockIdx.x * blockDim.x + threadIdx.x;
    if (i >= N) return;
    int bi = batch[i];
    int bprev = (i == 0) ? -1 : batch[i - 1];
    for (int g = bprev + 1; g <= bi; g++) g_segstart[g] = i;
    if (i == N - 1)
        for (int g = bi + 1; g <= B; g++) g_segstart[g] = N;
}

// ================= generic fp32 GEMM (small B-level matmuls) =================
__global__ void __launch_bounds__(256) gemm_kernel(
    const float* __restrict__ A, const float* __restrict__ Bm,
    const float* __restrict__ bias, float* __restrict__ C,
    int M, int Nn, int K, int relu)
{
    __shared__ __align__(16) float As[16][68];
    __shared__ __align__(16) float Bs[16][64];
    int tid = threadIdx.x;
    int mBase = blockIdx.y * 64, nBase = blockIdx.x * 64;
    int tx = tid & 15, ty = tid >> 4;

    float acc[4][4];
#pragma unroll
    for (int i2 = 0; i2 < 4; i2++)
#pragma unroll
        for (int j2 = 0; j2 < 4; j2++) acc[i2][j2] = 0.f;

    for (int kk = 0; kk < K; kk += 16) {
#pragma unroll
        for (int r = 0; r < 4; r++) {
            int idx = r * 256 + tid;
            int m = idx >> 4, k = idx & 15;
            int gm = mBase + m;
            As[k][m] = (gm < M) ? A[(size_t)gm * K + kk + k] : 0.f;
        }
#pragma unroll
        for (int r = 0; r < 4; r++) {
            int idx = r * 256 + tid;
            int k = idx >> 6, n = idx & 63;
            int gn = nBase + n;
            Bs[k][n] = (gn < Nn) ? Bm[(size_t)(kk + k) * Nn + gn] : 0.f;
        }
        __syncthreads();
#pragma unroll
        for (int k = 0; k < 16; k++) {
            float4 av = *(const float4*)&As[k][ty * 4];
            float4 bv = *(const float4*)&Bs[k][tx * 4];
            float am[4] = {av.x, av.y, av.z, av.w};
            float bn[4] = {bv.x, bv.y, bv.z, bv.w};
#pragma unroll
            for (int i2 = 0; i2 < 4; i2++)
#pragma unroll
                for (int j2 = 0; j2 < 4; j2++)
                    acc[i2][j2] += am[i2] * bn[j2];
        }
        __syncthreads();
    }
#pragma unroll
    for (int i2 = 0; i2 < 4; i2++) {
        int gm = mBase + ty * 4 + i2;
        if (gm >= M) continue;
#pragma unroll
        for (int j2 = 0; j2 < 4; j2++) {
            int gn = nBase + tx * 4 + j2;
            if (gn >= Nn) continue;
            float v = acc[i2][j2] + bias[gn];
            if (relu) v = fmaxf(v, 0.f);
            C[(size_t)gm * Nn + gn] = v;
        }
    }
}

// ================= HMMA scores kernel =================
// scores = relu(x @ W1a + t[batch]) @ W2 + b2 via bf16 hi/lo split (3 HMMA combos)
// Tile = 128 nodes x 64 cols x K=128. Persistent CTAs.
// Warps 0-3: mma + epilogue (32 rows each). Warps 4-7: stage next tile.

#define A_STRIDE   272                        // bytes/row (68 words; 68%32==4 -> conflict-free)
#define A_TILE_B   (128 * A_STRIDE)           // 34816
#define A_BUF_B    (2 * A_TILE_B)             // hi+lo = 69632
#define SM_BH      (2 * A_BUF_B)              // 139264
#define SM_BL      (SM_BH + 16384)            // 155648
#define SM_TOTAL_S (SM_BL + 16384)            // 172032

__device__ __forceinline__ void stage_tile(
    const float* __restrict__ x, int N, long base,
    char* sh, char* sl, int lt, int nt)
{
    for (int i = lt; i < 128 * 32; i += nt) {
        int m = i >> 5, c4 = i & 31;
        float4 v = make_float4(0.f, 0.f, 0.f, 0.f);
        long gi = base + m;
        if (gi < N) v = *(const float4*)(x + gi * 128 + c4 * 4);
        __nv_bfloat162 h01 = __floats2bfloat162_rn(v.x, v.y);
        __nv_bfloat162 h23 = __floats2bfloat162_rn(v.z, v.w);
        __nv_bfloat162 l01 = __floats2bfloat162_rn(v.x - __low2float(h01), v.y - __high2float(h01));
        __nv_bfloat162 l23 = __floats2bfloat162_rn(v.z - __low2float(h23), v.w - __high2float(h23));
        uint32_t off = m * A_STRIDE + c4 * 8;
        *(uint2*)(sh + off) = make_uint2(*(uint32_t*)&h01, *(uint32_t*)&h23);
        *(uint2*)(sl + off) = make_uint2(*(uint32_t*)&l01, *(uint32_t*)&l23);
    }
}

__global__ void __launch_bounds__(256, 1) scores_hmma_kernel(
    const float* __restrict__ x, const int* __restrict__ batch,
    const float* __restrict__ W1, const float* __restrict__ W2,
    const float* __restrict__ b2, int N)
{
    extern __shared__ __align__(1024) char smem[];
    uint32_t sbase = smem_u32(smem);
    int tid = threadIdx.x, wid = tid >> 5, lane = tid & 31;
    int g = lane >> 2, t = lane & 3;

    // ---- pre-pack B = W1a^T fragments in mma register order ----
    // entry idx = (kc*8 + nt)*32 + lane : uint2{b0,b1}
    for (int i = tid; i < 2048; i += 256) {
        int li = i & 31, nt = (i >> 5) & 7, kc = i >> 8;
        int gg = li >> 2, tt = li & 3;
        int n = nt * 8 + gg;
        int k0 = kc * 16 + 2 * tt;
        float w00 = W1[k0 * 64 + n],      w01 = W1[(k0 + 1) * 64 + n];
        float w10 = W1[(k0 + 8) * 64 + n], w11 = W1[(k0 + 9) * 64 + n];
        __nv_bfloat162 h0 = __floats2bfloat162_rn(w00, w01);
        __nv_bfloat162 h1 = __floats2bfloat162_rn(w10, w11);
        __nv_bfloat162 l0 = __floats2bfloat162_rn(w00 - __low2float(h0), w01 - __high2float(h0));
        __nv_bfloat162 l1 = __floats2bfloat162_rn(w10 - __low2float(h1), w11 - __high2float(h1));
        ((uint2*)(smem + SM_BH))[i] = make_uint2(*(uint32_t*)&h0, *(uint32_t*)&h1);
        ((uint2*)(smem + SM_BL))[i] = make_uint2(*(uint32_t*)&l0, *(uint32_t*)&l1);
    }

    // per-lane W2 fragment (cols nt*8+2t, +1)
    float2 w2r[8];
#pragma unroll
    for (int nt = 0; nt < 8; nt++)
        w2r[nt] = *(const float2*)(W2 + nt * 8 + 2 * t);
    float b2v = b2[0];

    int T = (N + 127) >> 7;
    int G = gridDim.x;
    int L = ((int)blockIdx.x < T) ? (T - (int)blockIdx.x + G - 1) / G : 0;

    // prologue: all threads stage tile 0 into buffer 0
    if (L > 0)
        stage_tile(x, N, (long)blockIdx.x * 128,
                   smem, smem + A_TILE_B, tid, 256);
    __syncthreads();

    // ldmatrix lane address pieces
    int lrow = lane & 15, lk = (lane >> 4) * 16;

    for (int j = 0; j < L; j++) {
        long base = ((long)blockIdx.x + (long)j * G) * 128;
        int buf = j & 1;

        if (wid >= 4) {
            // ---- loader warps: stage tile j+1 into the other buffer ----
            if (j + 1 < L) {
                long nb = ((long)blockIdx.x + (long)(j + 1) * G) * 128;
                char* dh = smem + (buf ^ 1) * A_BUF_B;
                stage_tile(x, N, nb, dh, dh + A_TILE_B, tid - 128, 128);
            }
        } else {
            // ---- mma warps: compute 32 rows ----
            uint32_t aBufH = sbase + buf * A_BUF_B;
            uint32_t aBufL = aBufH + A_TILE_B;
            uint32_t aoff0 = (wid * 32 + lrow) * A_STRIDE + lk;
            uint32_t aoff1 = aoff0 + 16 * A_STRIDE;

            float acc[2][8][4];
#pragma unroll
            for (int b = 0; b < 2; b++)
#pragma unroll
                for (int nt = 0; nt < 8; nt++)
#pragma unroll
                    for (int c = 0; c < 4; c++) acc[b][nt][c] = 0.f;

#pragma unroll
            for (int kc = 0; kc < 8; kc++) {
                uint32_t kb = kc * 32;
                uint32_t ah0[4], ah1[4], al0[4], al1[4];
                ldmat4(ah0, aBufH + aoff0 + kb);
                ldmat4(ah1, aBufH + aoff1 + kb);
                ldmat4(al0, aBufL + aoff0 + kb);
                ldmat4(al1, aBufL + aoff1 + kb);
                const uint2* bh = (const uint2*)(smem + SM_BH) + kc * 256 + lane;
                const uint2* bl = (const uint2*)(smem + SM_BL) + kc * 256 + lane;
#pragma unroll
                for (int nt = 0; nt < 8; nt++) {
                    uint2 bhv = bh[nt * 32];
                    uint2 blv = bl[nt * 32];
                    hmma(acc[0][nt], ah0, bhv.x, bhv.y);
                    hmma(acc[0][nt], ah0, blv.x, blv.y);
                    hmma(acc[0][nt], al0, bhv.x, bhv.y);
                    hmma(acc[1][nt], ah1, bhv.x, bhv.y);
                    hmma(acc[1][nt], ah1, blv.x, blv.y);
                    hmma(acc[1][nt], al1, bhv.x, bhv.y);
                }
            }

            // ---- epilogue: relu(acc + t[batch]) . W2, warp-reduce over t-lanes ----
#pragma unroll
            for (int b = 0; b < 2; b++) {
                long r0 = base + wid * 32 + b * 16 + g;
                long r1 = r0 + 8;
                int bi0 = (r0 < N) ? batch[r0] : 0;
                int bi1 = (r1 < N) ? batch[r1] : 0;
                const float* t0 = g_t + (size_t)bi0 * 64;
                const float* t1 = g_t + (size_t)bi1 * 64;
                float s0 = 0.f, s1 = 0.f;
#pragma unroll
                for (int nt = 0; nt < 8; nt++) {
                    int col = nt * 8 + 2 * t;
                    float2 tv0 = *(const float2*)(t0 + col);
                    float2 tv1 = *(const float2*)(t1 + col);
                    float2 w = w2r[nt];
                    s0 += fmaxf(acc[b][nt][0] + tv0.x, 0.f) * w.x
                        + fmaxf(acc[b][nt][1] + tv0.y, 0.f) * w.y;
                    s1 += fmaxf(acc[b][nt][2] + tv1.x, 0.f) * w.x
                        + fmaxf(acc[b][nt][3] + tv1.y, 0.f) * w.y;
                }
                s0 += __shfl_xor_sync(0xffffffffu, s0, 1);
                s0 += __shfl_xor_sync(0xffffffffu, s0, 2);
                s1 += __shfl_xor_sync(0xffffffffu, s1, 1);
                s1 += __shfl_xor_sync(0xffffffffu, s1, 2);
                if (t == 0) {
                    if (r0 < N) g_scores[r0] = s0 + b2v;
                    if (r1 < N) g_scores[r1] = s1 + b2v;
                }
            }
        }
        __syncthreads();
    }
}

// ================= per-graph softmax + weighted pooling =================
__global__ void __launch_bounds__(128) pool_kernel(
    const float* __restrict__ x, const float* __restrict__ u,
    float* __restrict__ attn, int N, int B)
{
    int g = blockIdx.x;
    int s = g_segstart[g], e = g_segstart[g + 1];
    int tid = threadIdx.x;
    int lane = tid & 31, wid = tid >> 5;
    __shared__ float red[4];

    float m = -INFINITY;
    for (int i = s + tid; i < e; i += 128) m = fmaxf(m, g_scores[i]);
#pragma unroll
    for (int o = 16; o; o >>= 1) m = fmaxf(m, __shfl_xor_sync(0xffffffffu, m, o));
    if (lane == 0) red[wid] = m;
    __syncthreads();
    m = fmaxf(fmaxf(red[0], red[1]), fmaxf(red[2], red[3]));
    __syncthreads();

    float ssum = 0.f;
    for (int i = s + tid; i < e; i += 128) ssum += expf(g_scores[i] - m);
#pragma unroll
    for (int o = 16; o; o >>= 1) ssum += __shfl_xor_sync(0xffffffffu, ssum, o);
    if (lane == 0) red[wid] = ssum;
    __syncthreads();
    float denom = red[0] + red[1] + red[2] + red[3];
    float inv = (denom > 0.f) ? 1.f / denom : 0.f;

    for (int i = s + tid; i < e; i += 128) attn[i] = expf(g_scores[i] - m) * inv;
    __syncthreads();

    float pool = 0.f;
    for (int i = s; i < e; i++) pool += attn[i] * x[(size_t)i * 128 + tid];
    g_x2[(size_t)g * 256 + tid]       = u[(size_t)g * 128 + tid];
    g_x2[(size_t)g * 256 + 128 + tid] = pool;
}

// ================= launch =================
extern "C" void kernel_launch(void* const* d_in, const int* in_sizes, int n_in,
                              void* d_out, int out_size)
{
    const float* x     = (const float*)d_in[0];
    const float* u     = (const float*)d_in[3];
    const int*   batch = (const int*)d_in[4];
    const float* W1    = (const float*)d_in[5];
    const float* b1    = (const float*)d_in[6];
    const float* W2    = (const float*)d_in[7];
    const float* b2    = (const float*)d_in[8];
    const float* Wg1   = (const float*)d_in[9];
    const float* bg1   = (const float*)d_in[10];
    const float* Wg2   = (const float*)d_in[11];
    const float* bg2   = (const float*)d_in[12];

    int N = in_sizes[0] / 128;
    int B = in_sizes[3] / 128;

    float* out  = (float*)d_out;
    float* attn = (float*)d_out + (size_t)B * 128;

    float *t_ptr, *x2_ptr, *h2_ptr;
    cudaGetSymbolAddress((void**)&t_ptr,  g_t);
    cudaGetSymbolAddress((void**)&x2_ptr, g_x2);
    cudaGetSymbolAddress((void**)&h2_ptr, g_h2);

    // 0) segment boundaries
    bounds_kernel<<<(N + 255) / 256, 256>>>(batch, N, B);

    // 1) t[B,64] = u @ W1b + b1
    {
        dim3 grid(1, (B + 63) / 64);
        gemm_kernel<<<grid, 256>>>(u, W1 + 128 * 64, b1, t_ptr, B, 64, 128, 0);
    }

    // 2) per-node scores via HMMA (bf16 split x3)
    cudaFuncSetAttribute(scores_hmma_kernel,
                         cudaFuncAttributeMaxDynamicSharedMemorySize, SM_TOTAL_S);
    {
        int T = (N + 127) / 128;
        int grid = T < 148 ? T : 148;
        scores_hmma_kernel<<<grid, 256, SM_TOTAL_S>>>(x, batch, W1, W2, b2, N);
    }

    // 3) segmented softmax + pooling, builds concat(u, pooled)
    pool_kernel<<<B, 128>>>(x, u, attn, N, B);

    // 4) global MLP
    {
        dim3 g3a(256 / 64, (B + 63) / 64);
        gemm_kernel<<<g3a, 256>>>(x2_ptr, Wg1, bg1, h2_ptr, B, 256, 256, 1);
        dim3 g3b(128 / 64, (B + 63) / 64);
        gemm_kernel<<<g3b, 256>>>(h2_ptr, Wg2, bg2, out, B, 128, 256, 0);
    }
}

// round 5
// speedup vs baseline: 1.6094x; 1.1172x over previous
#include <cuda_runtime.h>
#include <cuda_bf16.h>
#include <math.h>
#include <stdint.h>

#define NMAX 1000000
#define BMAX 16384

__device__ float g_t[BMAX * 64];        // t = u @ W1b + b1           [B,64]
__device__ float g_scores[NMAX];        // raw per-node scores        [N]
__device__ float g_x2[BMAX * 256];      // concat(u, pooled)          [B,256]
__device__ float g_h2[BMAX * 256];      // relu(x2@Wg1+bg1)           [B,256]
__device__ int   g_segstart[BMAX + 1];  // segment boundaries

// ================= helpers =================
__device__ __forceinline__ uint32_t smem_u32(const void* p) {
    uint32_t a;
    asm("{ .reg .u64 t; cvta.to.shared.u64 t, %1; cvt.u32.u64 %0, t; }" : "=r"(a) : "l"(p));
    return a;
}

__device__ __forceinline__ void ldmat4(uint32_t* r, uint32_t addr) {
    asm volatile("ldmatrix.sync.aligned.m8n8.x4.shared.b16 {%0,%1,%2,%3}, [%4];"
        : "=r"(r[0]), "=r"(r[1]), "=r"(r[2]), "=r"(r[3]) : "r"(addr));
}

__device__ __forceinline__ void hmma(float* c, const uint32_t* a, uint32_t b0, uint32_t b1) {
    asm volatile(
        "mma.sync.aligned.m16n8k16.row.col.f32.bf16.bf16.f32 "
        "{%0,%1,%2,%3}, {%4,%5,%6,%7}, {%8,%9}, {%0,%1,%2,%3};"
        : "+f"(c[0]), "+f"(c[1]), "+f"(c[2]), "+f"(c[3])
        : "r"(a[0]), "r"(a[1]), "r"(a[2]), "r"(a[3]), "r"(b0), "r"(b1));
}

// ================= segment boundaries =================
__global__ void bounds_kernel(const int* __restrict__ batch, int N, int B) {
    int i = blockIdx.x * blockDim.x + threadIdx.x;
    if (i >= N) return;
    int bi = batch[i];
    int bprev = (i == 0) ? -1 : batch[i - 1];
    for (int g = bprev + 1; g <= bi; g++) g_segstart[g] = i;
    if (i == N - 1)
        for (int g = bi + 1; g <= B; g++) g_segstart[g] = N;
}

// ================= shared tile geometry =================
#define A_STRIDE   272                        // bytes/row (68 words -> conflict-free ldmatrix)
#define A_TILE_B   (128 * A_STRIDE)           // 34816

// ================= HMMA split GEMM: C = [relu](A[M,K] @ Bw[K,Nn] + bias) =====
// Tile 128 x 64, K-chunks of 128, bf16 hi/lo split (3 HMMAs), 8 mma warps.
// Requires M%128==0, Nn%64==0, K%128==0 (true for all call sites).
#define GB_AH 0
#define GB_AL A_TILE_B
#define GB_BH (2 * A_TILE_B)                  // 69632
#define GB_BL (GB_BH + 16384)                 // 86016
#define GB_TOTAL (GB_BL + 16384)              // 102400

__global__ void __launch_bounds__(256) hmma_gemm(
    const float* __restrict__ A, const float* __restrict__ Bw,
    const float* __restrict__ bias, float* __restrict__ C,
    int M, int Nn, int K, int relu)
{
    extern __shared__ __align__(1024) char smem[];
    uint32_t sbase = smem_u32(smem);
    int tid = threadIdx.x, wid = tid >> 5, lane = tid & 31;
    int g = lane >> 2, t = lane & 3;
    int mBase = blockIdx.y * 128, nBase = blockIdx.x * 64;
    int lrow = lane & 15, lk = (lane >> 4) * 16;

    float acc[8][4];
#pragma unroll
    for (int nt = 0; nt < 8; nt++)
#pragma unroll
        for (int c = 0; c < 4; c++) acc[nt][c] = 0.f;

    for (int kb = 0; kb < K; kb += 128) {
        // ---- stage A chunk (128 rows x 128 k) hi/lo ----
        for (int i = tid; i < 128 * 32; i += 256) {
            int m = i >> 5, c4 = i & 31;
            float4 v = *(const float4*)(A + (size_t)(mBase + m) * K + kb + c4 * 4);
            __nv_bfloat162 h01 = __floats2bfloat162_rn(v.x, v.y);
            __nv_bfloat162 h23 = __floats2bfloat162_rn(v.z, v.w);
            __nv_bfloat162 l01 = __floats2bfloat162_rn(v.x - __low2float(h01), v.y - __high2float(h01));
            __nv_bfloat162 l23 = __floats2bfloat162_rn(v.z - __low2float(h23), v.w - __high2float(h23));
            uint32_t off = m * A_STRIDE + c4 * 8;
            *(uint2*)(smem + GB_AH + off) = make_uint2(*(uint32_t*)&h01, *(uint32_t*)&h23);
            *(uint2*)(smem + GB_AL + off) = make_uint2(*(uint32_t*)&l01, *(uint32_t*)&l23);
        }
        // ---- pack B chunk fragments (col-major operand) ----
        for (int i = tid; i < 2048; i += 256) {
            int li = i & 31, nt = (i >> 5) & 7, kcc = i >> 8;
            int n = nBase + nt * 8 + (li >> 2);
            int k0 = kb + kcc * 16 + 2 * (li & 3);
            float w00 = Bw[(size_t)k0 * Nn + n],       w01 = Bw[(size_t)(k0 + 1) * Nn + n];
            float w10 = Bw[(size_t)(k0 + 8) * Nn + n], w11 = Bw[(size_t)(k0 + 9) * Nn + n];
            __nv_bfloat162 h0 = __floats2bfloat162_rn(w00, w01);
            __nv_bfloat162 h1 = __floats2bfloat162_rn(w10, w11);
            __nv_bfloat162 l0 = __floats2bfloat162_rn(w00 - __low2float(h0), w01 - __high2float(h0));
            __nv_bfloat162 l1 = __floats2bfloat162_rn(w10 - __low2float(h1), w11 - __high2float(h1));
            ((uint2*)(smem + GB_BH))[i] = make_uint2(*(uint32_t*)&h0, *(uint32_t*)&h1);
            ((uint2*)(smem + GB_BL))[i] = make_uint2(*(uint32_t*)&l0, *(uint32_t*)&l1);
        }
        __syncthreads();

        uint32_t aH = sbase + GB_AH + (wid * 16 + lrow) * A_STRIDE + lk;
        uint32_t aL = aH + A_TILE_B;
#pragma unroll
        for (int kcc = 0; kcc < 8; kcc++) {
            uint32_t kb32 = kcc * 32;
            uint32_t ah[4], al[4];
            ldmat4(ah, aH + kb32);
            ldmat4(al, aL + kb32);
            const uint2* bh = (const uint2*)(smem + GB_BH) + kcc * 256 + lane;
            const uint2* bl = (const uint2*)(smem + GB_BL) + kcc * 256 + lane;
#pragma unroll
            for (int nt = 0; nt < 8; nt++) {
                uint2 bhv = bh[nt * 32];
                uint2 blv = bl[nt * 32];
                hmma(acc[nt], ah, bhv.x, bhv.y);
                hmma(acc[nt], ah, blv.x, blv.y);
                hmma(acc[nt], al, bhv.x, bhv.y);
            }
        }
        __syncthreads();
    }

    // ---- epilogue: bias, optional relu, store ----
    int row0 = mBase + wid * 16 + g;
    int row1 = row0 + 8;
#pragma unroll
    for (int nt = 0; nt < 8; nt++) {
        int col = nBase + nt * 8 + 2 * t;
        float2 bv = *(const float2*)(bias + col);
        float v00 = acc[nt][0] + bv.x, v01 = acc[nt][1] + bv.y;
        float v10 = acc[nt][2] + bv.x, v11 = acc[nt][3] + bv.y;
        if (relu) {
            v00 = fmaxf(v00, 0.f); v01 = fmaxf(v01, 0.f);
            v10 = fmaxf(v10, 0.f); v11 = fmaxf(v11, 0.f);
        }
        *(float2*)(C + (size_t)row0 * Nn + col) = make_float2(v00, v01);
        *(float2*)(C + (size_t)row1 * Nn + col) = make_float2(v10, v11);
    }
}

// ================= HMMA scores kernel =================
// scores = relu(x @ W1a + t[batch]) @ W2 + b2 via bf16 hi/lo split
#define A_BUF_B    (2 * A_TILE_B)             // hi+lo = 69632
#define SM_BH      (2 * A_BUF_B)              // 139264
#define SM_BL      (SM_BH + 16384)            // 155648
#define SM_TOTAL_S (SM_BL + 16384)            // 172032

__device__ __forceinline__ void stage_tile(
    const float* __restrict__ x, int N, long base,
    char* sh, char* sl, int lt, int nt)
{
    for (int i = lt; i < 128 * 32; i += nt) {
        int m = i >> 5, c4 = i & 31;
        float4 v = make_float4(0.f, 0.f, 0.f, 0.f);
        long gi = base + m;
        if (gi < N) v = *(const float4*)(x + gi * 128 + c4 * 4);
        __nv_bfloat162 h01 = __floats2bfloat162_rn(v.x, v.y);
        __nv_bfloat162 h23 = __floats2bfloat162_rn(v.z, v.w);
        __nv_bfloat162 l01 = __floats2bfloat162_rn(v.x - __low2float(h01), v.y - __high2float(h01));
        __nv_bfloat162 l23 = __floats2bfloat162_rn(v.z - __low2float(h23), v.w - __high2float(h23));
        uint32_t off = m * A_STRIDE + c4 * 8;
        *(uint2*)(sh + off) = make_uint2(*(uint32_t*)&h01, *(uint32_t*)&h23);
        *(uint2*)(sl + off) = make_uint2(*(uint32_t*)&l01, *(uint32_t*)&l23);
    }
}

__global__ void __launch_bounds__(256, 1) scores_hmma_kernel(
    const float* __restrict__ x, const int* __restrict__ batch,
    const float* __restrict__ W1, const float* __restrict__ W2,
    const float* __restrict__ b2, int N)
{
    extern __shared__ __align__(1024) char smem[];
    uint32_t sbase = smem_u32(smem);
    int tid = threadIdx.x, wid = tid >> 5, lane = tid & 31;
    int g = lane >> 2, t = lane & 3;

    // pre-pack B = W1a^T fragments in mma register order
    for (int i = tid; i < 2048; i += 256) {
        int li = i & 31, nt = (i >> 5) & 7, kc = i >> 8;
        int gg = li >> 2, tt = li & 3;
        int n = nt * 8 + gg;
        int k0 = kc * 16 + 2 * tt;
        float w00 = W1[k0 * 64 + n],       w01 = W1[(k0 + 1) * 64 + n];
        float w10 = W1[(k0 + 8) * 64 + n], w11 = W1[(k0 + 9) * 64 + n];
        __nv_bfloat162 h0 = __floats2bfloat162_rn(w00, w01);
        __nv_bfloat162 h1 = __floats2bfloat162_rn(w10, w11);
        __nv_bfloat162 l0 = __floats2bfloat162_rn(w00 - __low2float(h0), w01 - __high2float(h0));
        __nv_bfloat162 l1 = __floats2bfloat162_rn(w10 - __low2float(h1), w11 - __high2float(h1));
        ((uint2*)(smem + SM_BH))[i] = make_uint2(*(uint32_t*)&h0, *(uint32_t*)&h1);
        ((uint2*)(smem + SM_BL))[i] = make_uint2(*(uint32_t*)&l0, *(uint32_t*)&l1);
    }

    float2 w2r[8];
#pragma unroll
    for (int nt = 0; nt < 8; nt++)
        w2r[nt] = *(const float2*)(W2 + nt * 8 + 2 * t);
    float b2v = b2[0];

    int T = (N + 127) >> 7;
    int G = gridDim.x;
    int L = ((int)blockIdx.x < T) ? (T - (int)blockIdx.x + G - 1) / G : 0;

    if (L > 0)
        stage_tile(x, N, (long)blockIdx.x * 128, smem, smem + A_TILE_B, tid, 256);
    __syncthreads();

    int lrow = lane & 15, lk = (lane >> 4) * 16;

    for (int j = 0; j < L; j++) {
        long base = ((long)blockIdx.x + (long)j * G) * 128;
        int buf = j & 1;

        if (wid >= 4) {
            if (j + 1 < L) {
                long nb = ((long)blockIdx.x + (long)(j + 1) * G) * 128;
                char* dh = smem + (buf ^ 1) * A_BUF_B;
                stage_tile(x, N, nb, dh, dh + A_TILE_B, tid - 128, 128);
            }
        } else {
            uint32_t aBufH = sbase + buf * A_BUF_B;
            uint32_t aBufL = aBufH + A_TILE_B;
            uint32_t aoff0 = (wid * 32 + lrow) * A_STRIDE + lk;
            uint32_t aoff1 = aoff0 + 16 * A_STRIDE;

            float acc[2][8][4];
#pragma unroll
            for (int b = 0; b < 2; b++)
#pragma unroll
                for (int nt = 0; nt < 8; nt++)
#pragma unroll
                    for (int c = 0; c < 4; c++) acc[b][nt][c] = 0.f;

#pragma unroll
            for (int kc = 0; kc < 8; kc++) {
                uint32_t kb = kc * 32;
                uint32_t ah0[4], ah1[4], al0[4], al1[4];
                ldmat4(ah0, aBufH + aoff0 + kb);
                ldmat4(ah1, aBufH + aoff1 + kb);
                ldmat4(al0, aBufL + aoff0 + kb);
                ldmat4(al1, aBufL + aoff1 + kb);
                const uint2* bh = (const uint2*)(smem + SM_BH) + kc * 256 + lane;
                const uint2* bl = (const uint2*)(smem + SM_BL) + kc * 256 + lane;
#pragma unroll
                for (int nt = 0; nt < 8; nt++) {
                    uint2 bhv = bh[nt * 32];
                    uint2 blv = bl[nt * 32];
                    hmma(acc[0][nt], ah0, bhv.x, bhv.y);
                    hmma(acc[0][nt], ah0, blv.x, blv.y);
                    hmma(acc[0][nt], al0, bhv.x, bhv.y);
                    hmma(acc[1][nt], ah1, bhv.x, bhv.y);
                    hmma(acc[1][nt], ah1, blv.x, blv.y);
                    hmma(acc[1][nt], al1, bhv.x, bhv.y);
                }
            }

#pragma unroll
            for (int b = 0; b < 2; b++) {
                long r0 = base + wid * 32 + b * 16 + g;
                long r1 = r0 + 8;
                int bi0 = (r0 < N) ? batch[r0] : 0;
                int bi1 = (r1 < N) ? batch[r1] : 0;
                const float* t0 = g_t + (size_t)bi0 * 64;
                const float* t1 = g_t + (size_t)bi1 * 64;
                float s0 = 0.f, s1 = 0.f;
#pragma unroll
                for (int nt = 0; nt < 8; nt++) {
                    int col = nt * 8 + 2 * t;
                    float2 tv0 = *(const float2*)(t0 + col);
                    float2 tv1 = *(const float2*)(t1 + col);
                    float2 w = w2r[nt];
                    s0 += fmaxf(acc[b][nt][0] + tv0.x, 0.f) * w.x
                        + fmaxf(acc[b][nt][1] + tv0.y, 0.f) * w.y;
                    s1 += fmaxf(acc[b][nt][2] + tv1.x, 0.f) * w.x
                        + fmaxf(acc[b][nt][3] + tv1.y, 0.f) * w.y;
                }
                s0 += __shfl_xor_sync(0xffffffffu, s0, 1);
                s0 += __shfl_xor_sync(0xffffffffu, s0, 2);
                s1 += __shfl_xor_sync(0xffffffffu, s1, 1);
                s1 += __shfl_xor_sync(0xffffffffu, s1, 2);
                if (t == 0) {
                    if (r0 < N) g_scores[r0] = s0 + b2v;
                    if (r1 < N) g_scores[r1] = s1 + b2v;
                }
            }
        }
        __syncthreads();
    }
}

// ================= per-graph softmax + weighted pooling =================
__global__ void __launch_bounds__(128) pool_kernel(
    const float* __restrict__ x, const float* __restrict__ u,
    float* __restrict__ attn, int N, int B)
{
    int g = blockIdx.x;
    int s = g_segstart[g], e = g_segstart[g + 1];
    int tid = threadIdx.x;
    int lane = tid & 31, wid = tid >> 5;
    __shared__ float red[4];

    float m = -INFINITY;
    for (int i = s + tid; i < e; i += 128) m = fmaxf(m, g_scores[i]);
#pragma unroll
    for (int o = 16; o; o >>= 1) m = fmaxf(m, __shfl_xor_sync(0xffffffffu, m, o));
    if (lane == 0) red[wid] = m;
    __syncthreads();
    m = fmaxf(fmaxf(red[0], red[1]), fmaxf(red[2], red[3]));
    __syncthreads();

    float ssum = 0.f;
    for (int i = s + tid; i < e; i += 128) ssum += expf(g_scores[i] - m);
#pragma unroll
    for (int o = 16; o; o >>= 1) ssum += __shfl_xor_sync(0xffffffffu, ssum, o);
    if (lane == 0) red[wid] = ssum;
    __syncthreads();
    float denom = red[0] + red[1] + red[2] + red[3];
    float inv = (denom > 0.f) ? 1.f / denom : 0.f;

    for (int i = s + tid; i < e; i += 128) attn[i] = expf(g_scores[i] - m) * inv;
    __syncthreads();

    // weighted pool, unrolled x2 for MLP
    float p0 = 0.f, p1 = 0.f;
    int i = s;
    for (; i + 2 <= e; i += 2) {
        p0 += attn[i]     * x[(size_t)i * 128 + tid];
        p1 += attn[i + 1] * x[(size_t)(i + 1) * 128 + tid];
    }
    if (i < e) p0 += attn[i] * x[(size_t)i * 128 + tid];
    float pool = p0 + p1;
    g_x2[(size_t)g * 256 + tid]       = u[(size_t)g * 128 + tid];
    g_x2[(size_t)g * 256 + 128 + tid] = pool;
}

// ================= launch =================
extern "C" void kernel_launch(void* const* d_in, const int* in_sizes, int n_in,
                              void* d_out, int out_size)
{
    const float* x     = (const float*)d_in[0];
    const float* u     = (const float*)d_in[3];
    const int*   batch = (const int*)d_in[4];
    const float* W1    = (const float*)d_in[5];
    const float* b1    = (const float*)d_in[6];
    const float* W2    = (const float*)d_in[7];
    const float* b2    = (const float*)d_in[8];
    const float* Wg1   = (const float*)d_in[9];
    const float* bg1   = (const float*)d_in[10];
    const float* Wg2   = (const float*)d_in[11];
    const float* bg2   = (const float*)d_in[12];

    int N = in_sizes[0] / 128;
    int B = in_sizes[3] / 128;

    float* out  = (float*)d_out;
    float* attn = (float*)d_out + (size_t)B * 128;

    float *t_ptr, *x2_ptr, *h2_ptr;
    cudaGetSymbolAddress((void**)&t_ptr,  g_t);
    cudaGetSymbolAddress((void**)&x2_ptr, g_x2);
    cudaGetSymbolAddress((void**)&h2_ptr, g_h2);

    cudaFuncSetAttribute(hmma_gemm,
                         cudaFuncAttributeMaxDynamicSharedMemorySize, GB_TOTAL);
    cudaFuncSetAttribute(scores_hmma_kernel,
                         cudaFuncAttributeMaxDynamicSharedMemorySize, SM_TOTAL_S);

    // 0) segment boundaries
    bounds_kernel<<<(N + 255) / 256, 256>>>(batch, N, B);

    // 1) t[B,64] = u @ W1b + b1
    {
        dim3 grid(1, B / 128);
        hmma_gemm<<<grid, 256, GB_TOTAL>>>(u, W1 + 128 * 64, b1, t_ptr, B, 64, 128, 0);
    }

    // 2) per-node scores via HMMA (bf16 split x3)
    {
        int T = (N + 127) / 128;
        int grid = T < 148 ? T : 148;
        scores_hmma_kernel<<<grid, 256, SM_TOTAL_S>>>(x, batch, W1, W2, b2, N);
    }

    // 3) segmented softmax + pooling, builds concat(u, pooled)
    pool_kernel<<<B, 128>>>(x, u, attn, N, B);

    // 4) global MLP via HMMA split
    {
        dim3 g3a(256 / 64, B / 128);
        hmma_gemm<<<g3a, 256, GB_TOTAL>>>(x2_ptr, Wg1, bg1, h2_ptr, B, 256, 256, 1);
        dim3 g3b(128 / 64, B / 128);
        hmma_gemm<<<g3b, 256, GB_TOTAL>>>(h2_ptr, Wg2, bg2, out, B, 128, 256, 0);
    }
}

// round 6
// speedup vs baseline: 1.9358x; 1.2028x over previous
#include <cuda_runtime.h>
#include <cuda_bf16.h>
#include <math.h>
#include <stdint.h>

#define NMAX 1000000
#define BMAX 16384

__device__ float g_t[BMAX * 64];        // t = u @ W1b + b1           [B,64]
__device__ float g_scores[NMAX];        // raw per-node scores        [N]
__device__ float g_x2[BMAX * 256];      // concat(u, pooled)          [B,256]
__device__ float g_h2[BMAX * 256];      // relu(x2@Wg1+bg1)           [B,256]
__device__ int   g_segstart[BMAX + 1];  // segment boundaries

// ================= helpers =================
__device__ __forceinline__ uint32_t smem_u32(const void* p) {
    uint32_t a;
    asm("{ .reg .u64 t; cvta.to.shared.u64 t, %1; cvt.u32.u64 %0, t; }" : "=r"(a) : "l"(p));
    return a;
}

__device__ __forceinline__ void ldmat4(uint32_t* r, uint32_t addr) {
    asm volatile("ldmatrix.sync.aligned.m8n8.x4.shared.b16 {%0,%1,%2,%3}, [%4];"
        : "=r"(r[0]), "=r"(r[1]), "=r"(r[2]), "=r"(r[3]) : "r"(addr));
}

__device__ __forceinline__ void hmma(float* c, const uint32_t* a, uint32_t b0, uint32_t b1) {
    asm volatile(
        "mma.sync.aligned.m16n8k16.row.col.f32.bf16.bf16.f32 "
        "{%0,%1,%2,%3}, {%4,%5,%6,%7}, {%8,%9}, {%0,%1,%2,%3};"
        : "+f"(c[0]), "+f"(c[1]), "+f"(c[2]), "+f"(c[3])
        : "r"(a[0]), "r"(a[1]), "r"(a[2]), "r"(a[3]), "r"(b0), "r"(b1));
}

__device__ __forceinline__ void cp_async16(uint32_t dst, const void* src) {
    asm volatile("cp.async.cg.shared.global [%0], [%1], 16;" :: "r"(dst), "l"(src));
}
__device__ __forceinline__ void cp_commit() {
    asm volatile("cp.async.commit_group;" ::: "memory");
}
__device__ __forceinline__ void cp_wait0() {
    asm volatile("cp.async.wait_group 0;" ::: "memory");
}

// ================= segment boundaries =================
__global__ void bounds_kernel(const int* __restrict__ batch, int N, int B) {
    int i = blockIdx.x * blockDim.x + threadIdx.x;
    if (i >= N) return;
    int bi = batch[i];
    int bprev = (i == 0) ? -1 : batch[i - 1];
    for (int g = bprev + 1; g <= bi; g++) g_segstart[g] = i;
    if (i == N - 1)
        for (int g = bi + 1; g <= B; g++) g_segstart[g] = N;
}

// ================= shared tile geometry =================
#define A_STRIDE   272                        // bytes/row (68 words -> conflict-free ldmatrix)
#define A_TILE_B   (128 * A_STRIDE)           // 34816

// ================= HMMA split GEMM: C = [relu](A[M,K] @ Bw[K,Nn] + bias) =====
// Tile 128 x 64, bf16 hi/lo split (3 HMMAs), 8 mma warps, B packed ONCE (K<=256).
#define GB_AH 0
#define GB_AL A_TILE_B
#define GB_BH (2 * A_TILE_B)                  // 69632
#define GB_BL (GB_BH + 32768)                 // 102400
#define GB_TOTAL (GB_BL + 32768)              // 135168

__global__ void __launch_bounds__(256) hmma_gemm(
    const float* __restrict__ A, const float* __restrict__ Bw,
    const float* __restrict__ bias, float* __restrict__ C,
    int M, int Nn, int K, int relu)
{
    extern __shared__ __align__(1024) char smem[];
    uint32_t sbase = smem_u32(smem);
    int tid = threadIdx.x, wid = tid >> 5, lane = tid & 31;
    int g = lane >> 2, t = lane & 3;
    int mBase = blockIdx.y * 128, nBase = blockIdx.x * 64;
    int lrow = lane & 15, lk = (lane >> 4) * 16;

    // ---- pack ALL B fragments once (K/16 chunks x 8 nt x 32 lanes) ----
    int nEnt = (K >> 4) * 256;
    for (int i = tid; i < nEnt; i += 256) {
        int li = i & 31, nt = (i >> 5) & 7, kcc = i >> 8;
        int n = nBase + nt * 8 + (li >> 2);
        int k0 = kcc * 16 + 2 * (li & 3);
        float w00 = Bw[(size_t)k0 * Nn + n],       w01 = Bw[(size_t)(k0 + 1) * Nn + n];
        float w10 = Bw[(size_t)(k0 + 8) * Nn + n], w11 = Bw[(size_t)(k0 + 9) * Nn + n];
        __nv_bfloat162 h0 = __floats2bfloat162_rn(w00, w01);
        __nv_bfloat162 h1 = __floats2bfloat162_rn(w10, w11);
        __nv_bfloat162 l0 = __floats2bfloat162_rn(w00 - __low2float(h0), w01 - __high2float(h0));
        __nv_bfloat162 l1 = __floats2bfloat162_rn(w10 - __low2float(h1), w11 - __high2float(h1));
        ((uint2*)(smem + GB_BH))[i] = make_uint2(*(uint32_t*)&h0, *(uint32_t*)&h1);
        ((uint2*)(smem + GB_BL))[i] = make_uint2(*(uint32_t*)&l0, *(uint32_t*)&l1);
    }

    float acc[8][4];
#pragma unroll
    for (int nt = 0; nt < 8; nt++)
#pragma unroll
        for (int c = 0; c < 4; c++) acc[nt][c] = 0.f;

    for (int kb = 0; kb < K; kb += 128) {
        // ---- stage A chunk (128 rows x 128 k) hi/lo ----
        for (int i = tid; i < 128 * 32; i += 256) {
            int m = i >> 5, c4 = i & 31;
            float4 v = *(const float4*)(A + (size_t)(mBase + m) * K + kb + c4 * 4);
            __nv_bfloat162 h01 = __floats2bfloat162_rn(v.x, v.y);
            __nv_bfloat162 h23 = __floats2bfloat162_rn(v.z, v.w);
            __nv_bfloat162 l01 = __floats2bfloat162_rn(v.x - __low2float(h01), v.y - __high2float(h01));
            __nv_bfloat162 l23 = __floats2bfloat162_rn(v.z - __low2float(h23), v.w - __high2float(h23));
            uint32_t off = m * A_STRIDE + c4 * 8;
            *(uint2*)(smem + GB_AH + off) = make_uint2(*(uint32_t*)&h01, *(uint32_t*)&h23);
            *(uint2*)(smem + GB_AL + off) = make_uint2(*(uint32_t*)&l01, *(uint32_t*)&l23);
        }
        __syncthreads();

        uint32_t aH = sbase + GB_AH + (wid * 16 + lrow) * A_STRIDE + lk;
        uint32_t aL = aH + A_TILE_B;
        int kcBase = kb >> 4;
#pragma unroll
        for (int kcc = 0; kcc < 8; kcc++) {
            uint32_t ah[4], al[4];
            ldmat4(ah, aH + kcc * 32);
            ldmat4(al, aL + kcc * 32);
            const uint2* bh = (const uint2*)(smem + GB_BH) + (kcBase + kcc) * 256 + lane;
            const uint2* bl = (const uint2*)(smem + GB_BL) + (kcBase + kcc) * 256 + lane;
#pragma unroll
            for (int nt = 0; nt < 8; nt++) {
                uint2 bhv = bh[nt * 32];
                uint2 blv = bl[nt * 32];
                hmma(acc[nt], ah, bhv.x, bhv.y);
                hmma(acc[nt], ah, blv.x, blv.y);
                hmma(acc[nt], al, bhv.x, bhv.y);
            }
        }
        __syncthreads();
    }

    // ---- epilogue (each warp owns 16 rows) ----
    int row0 = mBase + wid * 16 + g;
    int row1 = row0 + 8;
#pragma unroll
    for (int nt = 0; nt < 8; nt++) {
        int col = nBase + nt * 8 + 2 * t;
        float2 bv = *(const float2*)(bias + col);
        float v00 = acc[nt][0] + bv.x, v01 = acc[nt][1] + bv.y;
        float v10 = acc[nt][2] + bv.x, v11 = acc[nt][3] + bv.y;
        if (relu) {
            v00 = fmaxf(v00, 0.f); v01 = fmaxf(v01, 0.f);
            v10 = fmaxf(v10, 0.f); v11 = fmaxf(v11, 0.f);
        }
        *(float2*)(C + (size_t)row0 * Nn + col) = make_float2(v00, v01);
        *(float2*)(C + (size_t)row1 * Nn + col) = make_float2(v10, v11);
    }
}

// ================= HMMA scores kernel v2 =================
// All 8 warps compute (16 rows each); cp.async staging of raw fp32 tile.
#define SC_SF 0
#define SC_AH 65536
#define SC_AL (SC_AH + A_TILE_B)              // 100352
#define SC_BH (SC_AL + A_TILE_B)              // 135168
#define SC_BL (SC_BH + 16384)                 // 151552
#define SC_TOTAL (SC_BL + 16384)              // 167936

__global__ void __launch_bounds__(256, 1) scores_hmma_kernel(
    const float* __restrict__ x, const int* __restrict__ batch,
    const float* __restrict__ W1, const float* __restrict__ W2,
    const float* __restrict__ b2, int N)
{
    extern __shared__ __align__(1024) char smem[];
    uint32_t sbase = smem_u32(smem);
    int tid = threadIdx.x, wid = tid >> 5, lane = tid & 31;
    int g = lane >> 2, t = lane & 3;
    int lrow = lane & 15, lk = (lane >> 4) * 16;

    // pre-pack B = W1a^T fragments in mma register order
    for (int i = tid; i < 2048; i += 256) {
        int li = i & 31, nt = (i >> 5) & 7, kc = i >> 8;
        int n = nt * 8 + (li >> 2);
        int k0 = kc * 16 + 2 * (li & 3);
        float w00 = W1[k0 * 64 + n],       w01 = W1[(k0 + 1) * 64 + n];
        float w10 = W1[(k0 + 8) * 64 + n], w11 = W1[(k0 + 9) * 64 + n];
        __nv_bfloat162 h0 = __floats2bfloat162_rn(w00, w01);
        __nv_bfloat162 h1 = __floats2bfloat162_rn(w10, w11);
        __nv_bfloat162 l0 = __floats2bfloat162_rn(w00 - __low2float(h0), w01 - __high2float(h0));
        __nv_bfloat162 l1 = __floats2bfloat162_rn(w10 - __low2float(h1), w11 - __high2float(h1));
        ((uint2*)(smem + SC_BH))[i] = make_uint2(*(uint32_t*)&h0, *(uint32_t*)&h1);
        ((uint2*)(smem + SC_BL))[i] = make_uint2(*(uint32_t*)&l0, *(uint32_t*)&l1);
    }

    float2 w2r[8];
#pragma unroll
    for (int nt = 0; nt < 8; nt++)
        w2r[nt] = *(const float2*)(W2 + nt * 8 + 2 * t);
    float b2v = b2[0];

    int T = (N + 127) >> 7;
    int G = gridDim.x;
    int L = ((int)blockIdx.x < T) ? (T - (int)blockIdx.x + G - 1) / G : 0;

    // ---- prologue: stage + convert tile 0 ----
    if (L > 0) {
        long base0 = (long)blockIdx.x * 128;
        for (int i = tid; i < 128 * 32; i += 256) {
            int m = i >> 5, c4 = i & 31;
            long gi = base0 + m;
            if (gi < N) cp_async16(sbase + SC_SF + m * 512 + c4 * 16, x + gi * 128 + c4 * 4);
        }
        cp_commit();
        cp_wait0();
        for (int i = tid; i < 128 * 32; i += 256) {
            int m = i >> 5, c4 = i & 31;
            float4 v = make_float4(0.f, 0.f, 0.f, 0.f);
            if (base0 + m < N) v = *(const float4*)(smem + SC_SF + m * 512 + c4 * 16);
            __nv_bfloat162 h01 = __floats2bfloat162_rn(v.x, v.y);
            __nv_bfloat162 h23 = __floats2bfloat162_rn(v.z, v.w);
            __nv_bfloat162 l01 = __floats2bfloat162_rn(v.x - __low2float(h01), v.y - __high2float(h01));
            __nv_bfloat162 l23 = __floats2bfloat162_rn(v.z - __low2float(h23), v.w - __high2float(h23));
            uint32_t off = m * A_STRIDE + c4 * 8;
            *(uint2*)(smem + SC_AH + off) = make_uint2(*(uint32_t*)&h01, *(uint32_t*)&h23);
            *(uint2*)(smem + SC_AL + off) = make_uint2(*(uint32_t*)&l01, *(uint32_t*)&l23);
        }
    }
    __syncthreads();

    for (int j = 0; j < L; j++) {
        long base = ((long)blockIdx.x + (long)j * G) * 128;

        // issue cp.async for tile j+1 (overlaps with compute below)
        if (j + 1 < L) {
            long nb = ((long)blockIdx.x + (long)(j + 1) * G) * 128;
            for (int i = tid; i < 128 * 32; i += 256) {
                int m = i >> 5, c4 = i & 31;
                long gi = nb + m;
                if (gi < N) cp_async16(sbase + SC_SF + m * 512 + c4 * 16, x + gi * 128 + c4 * 4);
            }
            cp_commit();
        }

        // ---- compute: each warp 16 rows ----
        uint32_t aH = sbase + SC_AH + (wid * 16 + lrow) * A_STRIDE + lk;
        uint32_t aL = aH + A_TILE_B;

        float acc[8][4];
#pragma unroll
        for (int nt = 0; nt < 8; nt++)
#pragma unroll
            for (int c = 0; c < 4; c++) acc[nt][c] = 0.f;

#pragma unroll
        for (int kc = 0; kc < 8; kc++) {
            uint32_t ah[4], al[4];
            ldmat4(ah, aH + kc * 32);
            ldmat4(al, aL + kc * 32);
            const uint2* bh = (const uint2*)(smem + SC_BH) + kc * 256 + lane;
            const uint2* bl = (const uint2*)(smem + SC_BL) + kc * 256 + lane;
#pragma unroll
            for (int nt = 0; nt < 8; nt++) {
                uint2 bhv = bh[nt * 32];
                uint2 blv = bl[nt * 32];
                hmma(acc[nt], ah, bhv.x, bhv.y);
                hmma(acc[nt], ah, blv.x, blv.y);
                hmma(acc[nt], al, bhv.x, bhv.y);
            }
        }

        // ---- epilogue: relu(acc + t[batch]) . W2, reduce over t-lanes ----
        {
            long r0 = base + wid * 16 + g;
            long r1 = r0 + 8;
            int bi0 = (r0 < N) ? batch[r0] : 0;
            int bi1 = (r1 < N) ? batch[r1] : 0;
            const float* t0 = g_t + (size_t)bi0 * 64;
            const float* t1 = g_t + (size_t)bi1 * 64;
            float s0 = 0.f, s1 = 0.f;
#pragma unroll
            for (int nt = 0; nt < 8; nt++) {
                int col = nt * 8 + 2 * t;
                float2 tv0 = *(const float2*)(t0 + col);
                float2 tv1 = *(const float2*)(t1 + col);
                float2 w = w2r[nt];
                s0 += fmaxf(acc[nt][0] + tv0.x, 0.f) * w.x
                    + fmaxf(acc[nt][1] + tv0.y, 0.f) * w.y;
                s1 += fmaxf(acc[nt][2] + tv1.x, 0.f) * w.x
                    + fmaxf(acc[nt][3] + tv1.y, 0.f) * w.y;
            }
            s0 += __shfl_xor_sync(0xffffffffu, s0, 1);
            s0 += __shfl_xor_sync(0xffffffffu, s0, 2);
            s1 += __shfl_xor_sync(0xffffffffu, s1, 1);
            s1 += __shfl_xor_sync(0xffffffffu, s1, 2);
            if (t == 0) {
                if (r0 < N) g_scores[r0] = s0 + b2v;
                if (r1 < N) g_scores[r1] = s1 + b2v;
            }
        }
        __syncthreads();   // everyone done reading AH/AL

        // ---- convert staged tile j+1 into AH/AL ----
        if (j + 1 < L) {
            cp_wait0();
            long nb = ((long)blockIdx.x + (long)(j + 1) * G) * 128;
            for (int i = tid; i < 128 * 32; i += 256) {
                int m = i >> 5, c4 = i & 31;
                float4 v = make_float4(0.f, 0.f, 0.f, 0.f);
                if (nb + m < N) v = *(const float4*)(smem + SC_SF + m * 512 + c4 * 16);
                __nv_bfloat162 h01 = __floats2bfloat162_rn(v.x, v.y);
                __nv_bfloat162 h23 = __floats2bfloat162_rn(v.z, v.w);
                __nv_bfloat162 l01 = __floats2bfloat162_rn(v.x - __low2float(h01), v.y - __high2float(h01));
                __nv_bfloat162 l23 = __floats2bfloat162_rn(v.z - __low2float(h23), v.w - __high2float(h23));
                uint32_t off = m * A_STRIDE + c4 * 8;
                *(uint2*)(smem + SC_AH + off) = make_uint2(*(uint32_t*)&h01, *(uint32_t*)&h23);
                *(uint2*)(smem + SC_AL + off) = make_uint2(*(uint32_t*)&l01, *(uint32_t*)&l23);
            }
        }
        __syncthreads();
    }
}

// ================= per-graph softmax + weighted pooling =================
__global__ void __launch_bounds__(128) pool_kernel(
    const float* __restrict__ x, const float* __restrict__ u,
    float* __restrict__ attn, int N, int B)
{
    int g = blockIdx.x;
    int s = g_segstart[g], e = g_segstart[g + 1];
    int tid = threadIdx.x;
    int lane = tid & 31, wid = tid >> 5;
    __shared__ float red[4];

    float m = -INFINITY;
    for (int i = s + tid; i < e; i += 128) m = fmaxf(m, g_scores[i]);
#pragma unroll
    for (int o = 16; o; o >>= 1) m = fmaxf(m, __shfl_xor_sync(0xffffffffu, m, o));
    if (lane == 0) red[wid] = m;
    __syncthreads();
    m = fmaxf(fmaxf(red[0], red[1]), fmaxf(red[2], red[3]));
    __syncthreads();

    float ssum = 0.f;
    for (int i = s + tid; i < e; i += 128) ssum += expf(g_scores[i] - m);
#pragma unroll
    for (int o = 16; o; o >>= 1) ssum += __shfl_xor_sync(0xffffffffu, ssum, o);
    if (lane == 0) red[wid] = ssum;
    __syncthreads();
    float denom = red[0] + red[1] + red[2] + red[3];
    float inv = (denom > 0.f) ? 1.f / denom : 0.f;

    for (int i = s + tid; i < e; i += 128) attn[i] = expf(g_scores[i] - m) * inv;
    __syncthreads();

    // weighted pool, unrolled x4
    float p0 = 0.f, p1 = 0.f, p2 = 0.f, p3 = 0.f;
    int i = s;
    for (; i + 4 <= e; i += 4) {
        p0 += attn[i]     * x[(size_t)i * 128 + tid];
        p1 += attn[i + 1] * x[(size_t)(i + 1) * 128 + tid];
        p2 += attn[i + 2] * x[(size_t)(i + 2) * 128 + tid];
        p3 += attn[i + 3] * x[(size_t)(i + 3) * 128 + tid];
    }
    for (; i < e; i++) p0 += attn[i] * x[(size_t)i * 128 + tid];
    float pool = (p0 + p1) + (p2 + p3);
    g_x2[(size_t)g * 256 + tid]       = u[(size_t)g * 128 + tid];
    g_x2[(size_t)g * 256 + 128 + tid] = pool;
}

// ================= launch =================
extern "C" void kernel_launch(void* const* d_in, const int* in_sizes, int n_in,
                              void* d_out, int out_size)
{
    const float* x     = (const float*)d_in[0];
    const float* u     = (const float*)d_in[3];
    const int*   batch = (const int*)d_in[4];
    const float* W1    = (const float*)d_in[5];
    const float* b1    = (const float*)d_in[6];
    const float* W2    = (const float*)d_in[7];
    const float* b2    = (const float*)d_in[8];
    const float* Wg1   = (const float*)d_in[9];
    const float* bg1   = (const float*)d_in[10];
    const float* Wg2   = (const float*)d_in[11];
    const float* bg2   = (const float*)d_in[12];

    int N = in_sizes[0] / 128;
    int B = in_sizes[3] / 128;

    float* out  = (float*)d_out;
    float* attn = (float*)d_out + (size_t)B * 128;

    float *t_ptr, *x2_ptr, *h2_ptr;
    cudaGetSymbolAddress((void**)&t_ptr,  g_t);
    cudaGetSymbolAddress((void**)&x2_ptr, g_x2);
    cudaGetSymbolAddress((void**)&h2_ptr, g_h2);

    cudaFuncSetAttribute(hmma_gemm,
                         cudaFuncAttributeMaxDynamicSharedMemorySize, GB_TOTAL);
    cudaFuncSetAttribute(scores_hmma_kernel,
                         cudaFuncAttributeMaxDynamicSharedMemorySize, SC_TOTAL);

    // 0) segment boundaries
    bounds_kernel<<<(N + 255) / 256, 256>>>(batch, N, B);

    // 1) t[B,64] = u @ W1b + b1
    {
        dim3 grid(1, B / 128);
        hmma_gemm<<<grid, 256, GB_TOTAL>>>(u, W1 + 128 * 64, b1, t_ptr, B, 64, 128, 0);
    }

    // 2) per-node scores via HMMA (bf16 split x3), cp.async pipeline
    {
        int T = (N + 127) / 128;
        int grid = T < 148 ? T : 148;
        scores_hmma_kernel<<<grid, 256, SC_TOTAL>>>(x, batch, W1, W2, b2, N);
    }

    // 3) segmented softmax + pooling, builds concat(u, pooled)
    pool_kernel<<<B, 128>>>(x, u, attn, N, B);

    // 4) global MLP via HMMA split
    {
        dim3 g3a(256 / 64, B / 128);
        hmma_gemm<<<g3a, 256, GB_TOTAL>>>(x2_ptr, Wg1, bg1, h2_ptr, B, 256, 256, 1);
        dim3 g3b(128 / 64, B / 128);
        hmma_gemm<<<g3b, 256, GB_TOTAL>>>(h2_ptr, Wg2, bg2, out, B, 128, 256, 0);
    }
}

// round 7
// speedup vs baseline: 2.1777x; 1.1250x over previous
#include <cuda_runtime.h>
#include <cuda_bf16.h>
#include <math.h>
#include <stdint.h>

#define NMAX 1000000
#define BMAX 16384

__device__ float g_t[BMAX * 64];        // t = u @ W1b + b1           [B,64]
__device__ float g_scores[NMAX];        // raw per-node scores        [N]
__device__ float g_x2[BMAX * 256];      // concat(u, pooled)          [B,256]
__device__ float g_h2[BMAX * 256];      // relu(x2@Wg1+bg1)           [B,256]
__device__ int   g_segstart[BMAX + 1];  // segment boundaries

// ================= helpers =================
__device__ __forceinline__ uint32_t smem_u32(const void* p) {
    uint32_t a;
    asm("{ .reg .u64 t; cvta.to.shared.u64 t, %1; cvt.u32.u64 %0, t; }" : "=r"(a) : "l"(p));
    return a;
}

__device__ __forceinline__ void ldmat4(uint32_t* r, uint32_t addr) {
    asm volatile("ldmatrix.sync.aligned.m8n8.x4.shared.b16 {%0,%1,%2,%3}, [%4];"
        : "=r"(r[0]), "=r"(r[1]), "=r"(r[2]), "=r"(r[3]) : "r"(addr));
}

__device__ __forceinline__ void hmma(float* c, const uint32_t* a, uint32_t b0, uint32_t b1) {
    asm volatile(
        "mma.sync.aligned.m16n8k16.row.col.f32.bf16.bf16.f32 "
        "{%0,%1,%2,%3}, {%4,%5,%6,%7}, {%8,%9}, {%0,%1,%2,%3};"
        : "+f"(c[0]), "+f"(c[1]), "+f"(c[2]), "+f"(c[3])
        : "r"(a[0]), "r"(a[1]), "r"(a[2]), "r"(a[3]), "r"(b0), "r"(b1));
}

// ================= segment boundaries =================
__global__ void bounds_kernel(const int* __restrict__ batch, int N, int B) {
    int i = blockIdx.x * blockDim.x + threadIdx.x;
    if (i >= N) return;
    int bi = batch[i];
    int bprev = (i == 0) ? -1 : batch[i - 1];
    for (int g = bprev + 1; g <= bi; g++) g_segstart[g] = i;
    if (i == N - 1)
        for (int g = bi + 1; g <= B; g++) g_segstart[g] = N;
}

// ================= shared tile geometry =================
#define A_STRIDE   272                        // bytes/row (68 words -> conflict-free ldmatrix)
#define A_TILE_B   (128 * A_STRIDE)           // 34816

// ================= HMMA split GEMM: C = [relu](A[M,K] @ Bw[K,Nn] + bias) =====
// Tile 128 x 64, bf16 hi/lo split (3 HMMAs), 8 mma warps, B packed ONCE (K<=256).
#define GB_AH 0
#define GB_AL A_TILE_B
#define GB_BH (2 * A_TILE_B)                  // 69632
#define GB_BL (GB_BH + 32768)                 // 102400
#define GB_TOTAL (GB_BL + 32768)              // 135168

__global__ void __launch_bounds__(256) hmma_gemm(
    const float* __restrict__ A, const float* __restrict__ Bw,
    const float* __restrict__ bias, float* __restrict__ C,
    int M, int Nn, int K, int relu)
{
    extern __shared__ __align__(1024) char smem[];
    uint32_t sbase = smem_u32(smem);
    int tid = threadIdx.x, wid = tid >> 5, lane = tid & 31;
    int g = lane >> 2, t = lane & 3;
    int mBase = blockIdx.y * 128, nBase = blockIdx.x * 64;
    int lrow = lane & 15, lk = (lane >> 4) * 16;

    // ---- pack ALL B fragments once ----
    int nEnt = (K >> 4) * 256;
    for (int i = tid; i < nEnt; i += 256) {
        int li = i & 31, nt = (i >> 5) & 7, kcc = i >> 8;
        int n = nBase + nt * 8 + (li >> 2);
        int k0 = kcc * 16 + 2 * (li & 3);
        float w00 = Bw[(size_t)k0 * Nn + n],       w01 = Bw[(size_t)(k0 + 1) * Nn + n];
        float w10 = Bw[(size_t)(k0 + 8) * Nn + n], w11 = Bw[(size_t)(k0 + 9) * Nn + n];
        __nv_bfloat162 h0 = __floats2bfloat162_rn(w00, w01);
        __nv_bfloat162 h1 = __floats2bfloat162_rn(w10, w11);
        __nv_bfloat162 l0 = __floats2bfloat162_rn(w00 - __low2float(h0), w01 - __high2float(h0));
        __nv_bfloat162 l1 = __floats2bfloat162_rn(w10 - __low2float(h1), w11 - __high2float(h1));
        ((uint2*)(smem + GB_BH))[i] = make_uint2(*(uint32_t*)&h0, *(uint32_t*)&h1);
        ((uint2*)(smem + GB_BL))[i] = make_uint2(*(uint32_t*)&l0, *(uint32_t*)&l1);
    }

    float acc[8][4];
#pragma unroll
    for (int nt = 0; nt < 8; nt++)
#pragma unroll
        for (int c = 0; c < 4; c++) acc[nt][c] = 0.f;

    for (int kb = 0; kb < K; kb += 128) {
        for (int i = tid; i < 128 * 32; i += 256) {
            int m = i >> 5, c4 = i & 31;
            float4 v = *(const float4*)(A + (size_t)(mBase + m) * K + kb + c4 * 4);
            __nv_bfloat162 h01 = __floats2bfloat162_rn(v.x, v.y);
            __nv_bfloat162 h23 = __floats2bfloat162_rn(v.z, v.w);
            __nv_bfloat162 l01 = __floats2bfloat162_rn(v.x - __low2float(h01), v.y - __high2float(h01));
            __nv_bfloat162 l23 = __floats2bfloat162_rn(v.z - __low2float(h23), v.w - __high2float(h23));
            uint32_t off = m * A_STRIDE + c4 * 8;
            *(uint2*)(smem + GB_AH + off) = make_uint2(*(uint32_t*)&h01, *(uint32_t*)&h23);
            *(uint2*)(smem + GB_AL + off) = make_uint2(*(uint32_t*)&l01, *(uint32_t*)&l23);
        }
        __syncthreads();

        uint32_t aH = sbase + GB_AH + (wid * 16 + lrow) * A_STRIDE + lk;
        uint32_t aL = aH + A_TILE_B;
        int kcBase = kb >> 4;
#pragma unroll
        for (int kcc = 0; kcc < 8; kcc++) {
            uint32_t ah[4], al[4];
            ldmat4(ah, aH + kcc * 32);
            ldmat4(al, aL + kcc * 32);
            const uint2* bh = (const uint2*)(smem + GB_BH) + (kcBase + kcc) * 256 + lane;
            const uint2* bl = (const uint2*)(smem + GB_BL) + (kcBase + kcc) * 256 + lane;
#pragma unroll
            for (int nt = 0; nt < 8; nt++) {
                uint2 bhv = bh[nt * 32];
                uint2 blv = bl[nt * 32];
                hmma(acc[nt], ah, bhv.x, bhv.y);
                hmma(acc[nt], ah, blv.x, blv.y);
                hmma(acc[nt], al, bhv.x, bhv.y);
            }
        }
        __syncthreads();
    }

    int row0 = mBase + wid * 16 + g;
    int row1 = row0 + 8;
#pragma unroll
    for (int nt = 0; nt < 8; nt++) {
        int col = nBase + nt * 8 + 2 * t;
        float2 bv = *(const float2*)(bias + col);
        float v00 = acc[nt][0] + bv.x, v01 = acc[nt][1] + bv.y;
        float v10 = acc[nt][2] + bv.x, v11 = acc[nt][3] + bv.y;
        if (relu) {
            v00 = fmaxf(v00, 0.f); v01 = fmaxf(v01, 0.f);
            v10 = fmaxf(v10, 0.f); v11 = fmaxf(v11, 0.f);
        }
        *(float2*)(C + (size_t)row0 * Nn + col) = make_float2(v00, v01);
        *(float2*)(C + (size_t)row1 * Nn + col) = make_float2(v10, v11);
    }
}

// ================= HMMA scores kernel v3 =================
// Direct LDG->cvt->STS (no staging buffer) => smem 100KB => 2 CTAs/SM.
// Cross-CTA overlap hides load/convert under the other CTA's MMA phase.
#define SC_AH 0
#define SC_AL A_TILE_B                        // 34816
#define SC_BH (2 * A_TILE_B)                  // 69632
#define SC_BL (SC_BH + 16384)                 // 86016
#define SC_TOTAL (SC_BL + 16384)              // 102400

__global__ void __launch_bounds__(256, 2) scores_hmma_kernel(
    const float* __restrict__ x, const int* __restrict__ batch,
    const float* __restrict__ W1, const float* __restrict__ W2,
    const float* __restrict__ b2, int N)
{
    extern __shared__ __align__(1024) char smem[];
    uint32_t sbase = smem_u32(smem);
    int tid = threadIdx.x, wid = tid >> 5, lane = tid & 31;
    int g = lane >> 2, t = lane & 3;
    int lrow = lane & 15, lk = (lane >> 4) * 16;

    // pre-pack B = W1a^T fragments in mma register order
    for (int i = tid; i < 2048; i += 256) {
        int li = i & 31, nt = (i >> 5) & 7, kc = i >> 8;
        int n = nt * 8 + (li >> 2);
        int k0 = kc * 16 + 2 * (li & 3);
        float w00 = W1[k0 * 64 + n],       w01 = W1[(k0 + 1) * 64 + n];
        float w10 = W1[(k0 + 8) * 64 + n], w11 = W1[(k0 + 9) * 64 + n];
        __nv_bfloat162 h0 = __floats2bfloat162_rn(w00, w01);
        __nv_bfloat162 h1 = __floats2bfloat162_rn(w10, w11);
        __nv_bfloat162 l0 = __floats2bfloat162_rn(w00 - __low2float(h0), w01 - __high2float(h0));
        __nv_bfloat162 l1 = __floats2bfloat162_rn(w10 - __low2float(h1), w11 - __high2float(h1));
        ((uint2*)(smem + SC_BH))[i] = make_uint2(*(uint32_t*)&h0, *(uint32_t*)&h1);
        ((uint2*)(smem + SC_BL))[i] = make_uint2(*(uint32_t*)&l0, *(uint32_t*)&l1);
    }

    float2 w2r[8];
#pragma unroll
    for (int nt = 0; nt < 8; nt++)
        w2r[nt] = *(const float2*)(W2 + nt * 8 + 2 * t);
    float b2v = b2[0];

    int T = (N + 127) >> 7;
    int G = gridDim.x;
    int L = ((int)blockIdx.x < T) ? (T - (int)blockIdx.x + G - 1) / G : 0;

    __syncthreads();

    int mRow = tid >> 5;           // this thread's first staged row (stride 8)
    int c4   = tid & 31;           // float4 column within row

    for (int j = 0; j < L; j++) {
        long base = ((long)blockIdx.x + (long)j * G) * 128;

        // ---- stage tile j: LDG (reg) -> hi/lo cvt -> STS ----
#pragma unroll
        for (int r = 0; r < 16; r++) {
            int m = mRow + r * 8;
            long gi = base + m;
            float4 v = make_float4(0.f, 0.f, 0.f, 0.f);
            if (gi < N) v = __ldg((const float4*)(x + gi * 128 + c4 * 4));
            __nv_bfloat162 h01 = __floats2bfloat162_rn(v.x, v.y);
            __nv_bfloat162 h23 = __floats2bfloat162_rn(v.z, v.w);
            __nv_bfloat162 l01 = __floats2bfloat162_rn(v.x - __low2float(h01), v.y - __high2float(h01));
            __nv_bfloat162 l23 = __floats2bfloat162_rn(v.z - __low2float(h23), v.w - __high2float(h23));
            uint32_t off = m * A_STRIDE + c4 * 8;
            *(uint2*)(smem + SC_AH + off) = make_uint2(*(uint32_t*)&h01, *(uint32_t*)&h23);
            *(uint2*)(smem + SC_AL + off) = make_uint2(*(uint32_t*)&l01, *(uint32_t*)&l23);
        }
        __syncthreads();

        // ---- compute: each warp 16 rows ----
        uint32_t aH = sbase + SC_AH + (wid * 16 + lrow) * A_STRIDE + lk;
        uint32_t aL = aH + A_TILE_B;

        float acc[8][4];
#pragma unroll
        for (int nt = 0; nt < 8; nt++)
#pragma unroll
            for (int c = 0; c < 4; c++) acc[nt][c] = 0.f;

#pragma unroll
        for (int kc = 0; kc < 8; kc++) {
            uint32_t ah[4], al[4];
            ldmat4(ah, aH + kc * 32);
            ldmat4(al, aL + kc * 32);
            const uint2* bh = (const uint2*)(smem + SC_BH) + kc * 256 + lane;
            const uint2* bl = (const uint2*)(smem + SC_BL) + kc * 256 + lane;
#pragma unroll
            for (int nt = 0; nt < 8; nt++) {
                uint2 bhv = bh[nt * 32];
                uint2 blv = bl[nt * 32];
                hmma(acc[nt], ah, bhv.x, bhv.y);
                hmma(acc[nt], ah, blv.x, blv.y);
                hmma(acc[nt], al, bhv.x, bhv.y);
            }
        }

        // ---- epilogue: relu(acc + t[batch]) . W2, reduce over t-lanes ----
        {
            long r0 = base + wid * 16 + g;
            long r1 = r0 + 8;
            int bi0 = (r0 < N) ? batch[r0] : 0;
            int bi1 = (r1 < N) ? batch[r1] : 0;
            const float* t0 = g_t + (size_t)bi0 * 64;
            const float* t1 = g_t + (size_t)bi1 * 64;
            float s0 = 0.f, s1 = 0.f;
#pragma unroll
            for (int nt = 0; nt < 8; nt++) {
                int col = nt * 8 + 2 * t;
                float2 tv0 = *(const float2*)(t0 + col);
                float2 tv1 = *(const float2*)(t1 + col);
                float2 w = w2r[nt];
                s0 += fmaxf(acc[nt][0] + tv0.x, 0.f) * w.x
                    + fmaxf(acc[nt][1] + tv0.y, 0.f) * w.y;
                s1 += fmaxf(acc[nt][2] + tv1.x, 0.f) * w.x
                    + fmaxf(acc[nt][3] + tv1.y, 0.f) * w.y;
            }
            s0 += __shfl_xor_sync(0xffffffffu, s0, 1);
            s0 += __shfl_xor_sync(0xffffffffu, s0, 2);
            s1 += __shfl_xor_sync(0xffffffffu, s1, 1);
            s1 += __shfl_xor_sync(0xffffffffu, s1, 2);
            if (t == 0) {
                if (r0 < N) g_scores[r0] = s0 + b2v;
                if (r1 < N) g_scores[r1] = s1 + b2v;
            }
        }
        __syncthreads();
    }
}

// ================= per-graph softmax + weighted pooling =================
__global__ void __launch_bounds__(128) pool_kernel(
    const float* __restrict__ x, const float* __restrict__ u,
    float* __restrict__ attn, int N, int B)
{
    int g = blockIdx.x;
    int s = g_segstart[g], e = g_segstart[g + 1];
    int tid = threadIdx.x;
    int lane = tid & 31, wid = tid >> 5;
    __shared__ float red[4];

    float m = -INFINITY;
    for (int i = s + tid; i < e; i += 128) m = fmaxf(m, g_scores[i]);
#pragma unroll
    for (int o = 16; o; o >>= 1) m = fmaxf(m, __shfl_xor_sync(0xffffffffu, m, o));
    if (lane == 0) red[wid] = m;
    __syncthreads();
    m = fmaxf(fmaxf(red[0], red[1]), fmaxf(red[2], red[3]));
    __syncthreads();

    float ssum = 0.f;
    for (int i = s + tid; i < e; i += 128) ssum += expf(g_scores[i] - m);
#pragma unroll
    for (int o = 16; o; o >>= 1) ssum += __shfl_xor_sync(0xffffffffu, ssum, o);
    if (lane == 0) red[wid] = ssum;
    __syncthreads();
    float denom = red[0] + red[1] + red[2] + red[3];
    float inv = (denom > 0.f) ? 1.f / denom : 0.f;

    for (int i = s + tid; i < e; i += 128) attn[i] = expf(g_scores[i] - m) * inv;
    __syncthreads();

    // weighted pool, unrolled x2, streaming loads
    float p0 = 0.f, p1 = 0.f;
    int i = s;
    for (; i + 2 <= e; i += 2) {
        p0 += attn[i]     * __ldcs(x + (size_t)i * 128 + tid);
        p1 += attn[i + 1] * __ldcs(x + (size_t)(i + 1) * 128 + tid);
    }
    if (i < e) p0 += attn[i] * __ldcs(x + (size_t)i * 128 + tid);
    float pool = p0 + p1;
    g_x2[(size_t)g * 256 + tid]       = u[(size_t)g * 128 + tid];
    g_x2[(size_t)g * 256 + 128 + tid] = pool;
}

// ================= launch =================
extern "C" void kernel_launch(void* const* d_in, const int* in_sizes, int n_in,
                              void* d_out, int out_size)
{
    const float* x     = (const float*)d_in[0];
    const float* u     = (const float*)d_in[3];
    const int*   batch = (const int*)d_in[4];
    const float* W1    = (const float*)d_in[5];
    const float* b1    = (const float*)d_in[6];
    const float* W2    = (const float*)d_in[7];
    const float* b2    = (const float*)d_in[8];
    const float* Wg1   = (const float*)d_in[9];
    const float* bg1   = (const float*)d_in[10];
    const float* Wg2   = (const float*)d_in[11];
    const float* bg2   = (const float*)d_in[12];

    int N = in_sizes[0] / 128;
    int B = in_sizes[3] / 128;

    float* out  = (float*)d_out;
    float* attn = (float*)d_out + (size_t)B * 128;

    float *t_ptr, *x2_ptr, *h2_ptr;
    cudaGetSymbolAddress((void**)&t_ptr,  g_t);
    cudaGetSymbolAddress((void**)&x2_ptr, g_x2);
    cudaGetSymbolAddress((void**)&h2_ptr, g_h2);

    cudaFuncSetAttribute(hmma_gemm,
                         cudaFuncAttributeMaxDynamicSharedMemorySize, GB_TOTAL);
    cudaFuncSetAttribute(scores_hmma_kernel,
                         cudaFuncAttributeMaxDynamicSharedMemorySize, SC_TOTAL);

    // 0) segment boundaries
    bounds_kernel<<<(N + 255) / 256, 256>>>(batch, N, B);

    // 1) t[B,64] = u @ W1b + b1
    {
        dim3 grid(1, B / 128);
        hmma_gemm<<<grid, 256, GB_TOTAL>>>(u, W1 + 128 * 64, b1, t_ptr, B, 64, 128, 0);
    }

    // 2) per-node scores via HMMA (bf16 split x3), 2 CTAs/SM
    {
        int T = (N + 127) / 128;
        int grid = T < 296 ? T : 296;
        scores_hmma_kernel<<<grid, 256, SC_TOTAL>>>(x, batch, W1, W2, b2, N);
    }

    // 3) segmented softmax + pooling, builds concat(u, pooled)
    pool_kernel<<<B, 128>>>(x, u, attn, N, B);

    // 4) global MLP via HMMA split
    {
        dim3 g3a(256 / 64, B / 128);
        hmma_gemm<<<g3a, 256, GB_TOTAL>>>(x2_ptr, Wg1, bg1, h2_ptr, B, 256, 256, 1);
        dim3 g3b(128 / 64, B / 128);
        hmma_gemm<<<g3b, 256, GB_TOTAL>>>(h2_ptr, Wg2, bg2, out, B, 128, 256, 0);
    }
}